// round 9
// baseline (speedup 1.0000x reference)
#include <cuda_runtime.h>

#define HID   50
#define SEQT  512
#define NGRP  4            // 64-thread groups per block
#define NSTR  3            // batch elements (streams) per group
#define NB    (NGRP*NSTR)  // 12 batch elements per block
#define BLOCK 256
#define ROWP  52           // padded h row (floats)

// packed 2xfp32 FMA: d = a*b + c
__device__ __forceinline__ unsigned long long fma2(unsigned long long a,
                                                   unsigned long long b,
                                                   unsigned long long c) {
    unsigned long long d;
    asm("fma.rn.f32x2 %0, %1, %2, %3;" : "=l"(d) : "l"(a), "l"(b), "l"(c));
    return d;
}
__device__ __forceinline__ float hsum2(unsigned long long v) {
    float lo, hi;
    asm("mov.b64 {%0, %1}, %2;" : "=f"(lo), "=f"(hi) : "l"(v));
    return lo + hi;
}
__device__ __forceinline__ float tanhapx(float x) {
    float y;
    asm("tanh.approx.f32 %0, %1;" : "=f"(y) : "f"(x));
    return y;
}
__device__ __forceinline__ float sigapx(float x) {
    return __fmaf_rn(0.5f, tanhapx(0.5f * x), 0.5f);
}
// named barrier over one 64-thread group (2 warps)
__device__ __forceinline__ void group_bar(int id) {
    asm volatile("bar.sync %0, 64;" :: "r"(id) : "memory");
}

__global__ void __launch_bounds__(BLOCK, 1)
lstm_fused_kernel(const float* __restrict__ x,
                  const float* __restrict__ W_ih,
                  const float* __restrict__ W_hh,
                  const float* __restrict__ b_ih,
                  const float* __restrict__ b_hh,
                  const float* __restrict__ W_out,
                  const float* __restrict__ b_out,
                  float* __restrict__ out,
                  int B)
{
    // h rows: stream A of group g -> row g, B -> g+4, C -> g+8
    __shared__ __align__(16) float sh_h[2][NB][ROWP];
    __shared__ __align__(16) float sh_wout[ROWP];

    const int tid = threadIdx.x;
    const int g   = tid >> 6;          // group 0..3
    const int r   = tid & 63;          // lane in group
    const int j   = r;                 // hidden unit (gate lanes r<50)
    const bool gate_lane = (r < HID);

    const int base = blockIdx.x * NB;
    const int bA = base + g;
    const int bB = bA + NGRP;
    const int bC = bA + 2 * NGRP;
    const bool actA = (bA < B);
    const bool actB = (bB < B);
    const bool actC = (bC < B);

    // out lanes: r = 50,51,52 -> streams A,B,C of this group
    const int  os      = r - HID;                       // 0..2 if out lane
    const bool out_lane = gate_lane ? false : (os < NSTR) && (base + os * NGRP + g < B);
    const int  oelem   = out_lane ? (base + os * NGRP + g) : 0;
    const int  orowidx = os * NGRP + g;                 // h row for this out lane

    // ---- one-time init ----
    for (int i = tid; i < 2 * NB * ROWP; i += BLOCK)
        (&sh_h[0][0][0])[i] = 0.0f;
    if (tid < ROWP)
        sh_wout[tid] = (tid < HID) ? W_out[tid] : 0.0f;

    // 4 W_hh gate rows for unit j, f32 pairs (shared by all 3 streams)
    unsigned long long w2[4][25];
    float wih[4], bs[4];
    if (gate_lane) {
        #pragma unroll
        for (int gg = 0; gg < 4; gg++) {
            const int row = gg * HID + j;   // PyTorch gate order: i, f, g, o
            wih[gg] = W_ih[row];
            bs[gg]  = b_ih[row] + b_hh[row];
            const unsigned long long* wrow =
                reinterpret_cast<const unsigned long long*>(W_hh + row * HID);
            #pragma unroll
            for (int p = 0; p < 25; p++)
                w2[gg][p] = wrow[p];
        }
    }
    const float bout = b_out[0];

    const float* __restrict__ xrowA = x + (size_t)(actA ? bA : 0) * SEQT;
    const float* __restrict__ xrowB = x + (size_t)(actB ? bB : 0) * SEQT;
    const float* __restrict__ xrowC = x + (size_t)(actC ? bC : 0) * SEQT;
    float* __restrict__ orow = out + (size_t)oelem * SEQT;

    float cA = 0.0f, cB = 0.0f, cC = 0.0f;
    int cur = 0;

    __syncthreads();                 // init visible to all groups (once)

    const int barid = g + 1;         // named barrier ids 1..4

    for (int t = 0; t < SEQT; t++) {
        const int nxt = cur ^ 1;

        if (gate_lane) {
            const float xA = xrowA[t];
            const float xB = xrowB[t];
            const float xC = xrowC[t];

            const float* hA = &sh_h[cur][g][0];  // B at +NGRP*ROWP, C at +2*NGRP*ROWP
            unsigned long long aA0=0ull,aA1=0ull,aA2=0ull,aA3=0ull;
            unsigned long long aB0=0ull,aB1=0ull,aB2=0ull,aB3=0ull;
            unsigned long long aC0=0ull,aC1=0ull,aC2=0ull,aC3=0ull;

            #pragma unroll
            for (int q = 0; q < 12; q++) {
                const ulonglong2 hvA = *reinterpret_cast<const ulonglong2*>(hA + q*4);
                const ulonglong2 hvB = *reinterpret_cast<const ulonglong2*>(hA + NGRP*ROWP + q*4);
                const ulonglong2 hvC = *reinterpret_cast<const ulonglong2*>(hA + 2*NGRP*ROWP + q*4);
                aA0 = fma2(hvA.x, w2[0][2*q],   aA0);
                aB0 = fma2(hvB.x, w2[0][2*q],   aB0);
                aC0 = fma2(hvC.x, w2[0][2*q],   aC0);
                aA1 = fma2(hvA.x, w2[1][2*q],   aA1);
                aB1 = fma2(hvB.x, w2[1][2*q],   aB1);
                aC1 = fma2(hvC.x, w2[1][2*q],   aC1);
                aA2 = fma2(hvA.x, w2[2][2*q],   aA2);
                aB2 = fma2(hvB.x, w2[2][2*q],   aB2);
                aC2 = fma2(hvC.x, w2[2][2*q],   aC2);
                aA3 = fma2(hvA.x, w2[3][2*q],   aA3);
                aB3 = fma2(hvB.x, w2[3][2*q],   aB3);
                aC3 = fma2(hvC.x, w2[3][2*q],   aC3);
                aA0 = fma2(hvA.y, w2[0][2*q+1], aA0);
                aB0 = fma2(hvB.y, w2[0][2*q+1], aB0);
                aC0 = fma2(hvC.y, w2[0][2*q+1], aC0);
                aA1 = fma2(hvA.y, w2[1][2*q+1], aA1);
                aB1 = fma2(hvB.y, w2[1][2*q+1], aB1);
                aC1 = fma2(hvC.y, w2[1][2*q+1], aC1);
                aA2 = fma2(hvA.y, w2[2][2*q+1], aA2);
                aB2 = fma2(hvB.y, w2[2][2*q+1], aB2);
                aC2 = fma2(hvC.y, w2[2][2*q+1], aC2);
                aA3 = fma2(hvA.y, w2[3][2*q+1], aA3);
                aB3 = fma2(hvB.y, w2[3][2*q+1], aB3);
                aC3 = fma2(hvC.y, w2[3][2*q+1], aC3);
            }
            {
                const unsigned long long hvA = *reinterpret_cast<const unsigned long long*>(hA + 48);
                const unsigned long long hvB = *reinterpret_cast<const unsigned long long*>(hA + NGRP*ROWP + 48);
                const unsigned long long hvC = *reinterpret_cast<const unsigned long long*>(hA + 2*NGRP*ROWP + 48);
                aA0 = fma2(hvA, w2[0][24], aA0);
                aB0 = fma2(hvB, w2[0][24], aB0);
                aC0 = fma2(hvC, w2[0][24], aC0);
                aA1 = fma2(hvA, w2[1][24], aA1);
                aB1 = fma2(hvB, w2[1][24], aB1);
                aC1 = fma2(hvC, w2[1][24], aC1);
                aA2 = fma2(hvA, w2[2][24], aA2);
                aB2 = fma2(hvB, w2[2][24], aB2);
                aC2 = fma2(hvC, w2[2][24], aC2);
                aA3 = fma2(hvA, w2[3][24], aA3);
                aB3 = fma2(hvB, w2[3][24], aB3);
                aC3 = fma2(hvC, w2[3][24], aC3);
            }

            // stream A
            {
                const float g0 = hsum2(aA0) + __fmaf_rn(xA, wih[0], bs[0]);
                const float g1 = hsum2(aA1) + __fmaf_rn(xA, wih[1], bs[1]);
                const float g2 = hsum2(aA2) + __fmaf_rn(xA, wih[2], bs[2]);
                const float g3 = hsum2(aA3) + __fmaf_rn(xA, wih[3], bs[3]);
                const float ig = sigapx(g0), fg = sigapx(g1);
                const float gg = tanhapx(g2), og = sigapx(g3);
                cA = __fmaf_rn(fg, cA, ig * gg);
                if (actA) sh_h[nxt][g][j] = og * tanhapx(cA);
            }
            // stream B
            {
                const float g0 = hsum2(aB0) + __fmaf_rn(xB, wih[0], bs[0]);
                const float g1 = hsum2(aB1) + __fmaf_rn(xB, wih[1], bs[1]);
                const float g2 = hsum2(aB2) + __fmaf_rn(xB, wih[2], bs[2]);
                const float g3 = hsum2(aB3) + __fmaf_rn(xB, wih[3], bs[3]);
                const float ig = sigapx(g0), fg = sigapx(g1);
                const float gg = tanhapx(g2), og = sigapx(g3);
                cB = __fmaf_rn(fg, cB, ig * gg);
                if (actB) sh_h[nxt][g + NGRP][j] = og * tanhapx(cB);
            }
            // stream C
            {
                const float g0 = hsum2(aC0) + __fmaf_rn(xC, wih[0], bs[0]);
                const float g1 = hsum2(aC1) + __fmaf_rn(xC, wih[1], bs[1]);
                const float g2 = hsum2(aC2) + __fmaf_rn(xC, wih[2], bs[2]);
                const float g3 = hsum2(aC3) + __fmaf_rn(xC, wih[3], bs[3]);
                const float ig = sigapx(g0), fg = sigapx(g1);
                const float gg = tanhapx(g2), og = sigapx(g3);
                cC = __fmaf_rn(fg, cC, ig * gg);
                if (actC) sh_h[nxt][g + 2*NGRP][j] = og * tanhapx(cC);
            }
        } else if (out_lane && t > 0) {
            // out[t-1] from the read buffer, concurrent with gate compute
            const float* hp = &sh_h[cur][orowidx][0];
            float y0 = bout, y1 = 0.0f, y2 = 0.0f, y3 = 0.0f;
            #pragma unroll
            for (int kq = 0; kq < 13; kq++) {       // pads are zero in both
                const float4 hv = *reinterpret_cast<const float4*>(hp + kq * 4);
                const float4 wv = *reinterpret_cast<const float4*>(sh_wout + kq * 4);
                y0 = __fmaf_rn(hv.x, wv.x, y0);
                y1 = __fmaf_rn(hv.y, wv.y, y1);
                y2 = __fmaf_rn(hv.z, wv.z, y2);
                y3 = __fmaf_rn(hv.w, wv.w, y3);
            }
            orow[t - 1] = (y0 + y1) + (y2 + y3);
        }

        group_bar(barid);
        cur = nxt;
    }

    if (out_lane) {
        const float* hp = &sh_h[cur][orowidx][0];
        float y0 = bout, y1 = 0.0f, y2 = 0.0f, y3 = 0.0f;
        #pragma unroll
        for (int kq = 0; kq < 13; kq++) {
            const float4 hv = *reinterpret_cast<const float4*>(hp + kq * 4);
            const float4 wv = *reinterpret_cast<const float4*>(sh_wout + kq * 4);
            y0 = __fmaf_rn(hv.x, wv.x, y0);
            y1 = __fmaf_rn(hv.y, wv.y, y1);
            y2 = __fmaf_rn(hv.z, wv.z, y2);
            y3 = __fmaf_rn(hv.w, wv.w, y3);
        }
        orow[SEQT - 1] = (y0 + y1) + (y2 + y3);
    }
}

extern "C" void kernel_launch(void* const* d_in, const int* in_sizes, int n_in,
                              void* d_out, int out_size)
{
    const float* x     = (const float*)d_in[0];
    const float* W_ih  = (const float*)d_in[1];
    const float* W_hh  = (const float*)d_in[2];
    const float* b_ih  = (const float*)d_in[3];
    const float* b_hh  = (const float*)d_in[4];
    const float* W_out = (const float*)d_in[5];
    const float* b_out = (const float*)d_in[6];
    float* out = (float*)d_out;

    const int B = in_sizes[0] / SEQT;          // I == 1, x is [B, T, 1]
    const int grid = (B + NB - 1) / NB;
    lstm_fused_kernel<<<grid, BLOCK>>>(x, W_ih, W_hh, b_ih, b_hh, W_out, b_out, out, B);
}

// round 10
// speedup vs baseline: 1.2050x; 1.2050x over previous
#include <cuda_runtime.h>

#define HID   50
#define SEQT  512
#define NG    5            // unit-groups per block
#define NB    10           // batch elements per block (2 streams per group)
#define BLOCK 256          // 250 active lanes
#define ROWP  52           // padded h row (floats)

// packed 2xfp32 FMA: d = a*b + c
__device__ __forceinline__ unsigned long long fma2(unsigned long long a,
                                                   unsigned long long b,
                                                   unsigned long long c) {
    unsigned long long d;
    asm("fma.rn.f32x2 %0, %1, %2, %3;" : "=l"(d) : "l"(a), "l"(b), "l"(c));
    return d;
}
__device__ __forceinline__ float hsum2(unsigned long long v) {
    float lo, hi;
    asm("mov.b64 {%0, %1}, %2;" : "=f"(lo), "=f"(hi) : "l"(v));
    return lo + hi;
}
__device__ __forceinline__ float tanhapx(float x) {
    float y;
    asm("tanh.approx.f32 %0, %1;" : "=f"(y) : "f"(x));
    return y;
}
__device__ __forceinline__ float sigapx(float x) {
    return __fmaf_rn(0.5f, tanhapx(0.5f * x), 0.5f);
}

__global__ void __launch_bounds__(BLOCK, 1)
lstm_fused_kernel(const float* __restrict__ x,
                  const float* __restrict__ W_ih,
                  const float* __restrict__ W_hh,
                  const float* __restrict__ b_ih,
                  const float* __restrict__ b_hh,
                  const float* __restrict__ W_out,
                  const float* __restrict__ b_out,
                  float* __restrict__ out,
                  int B)
{
    // h rows 0..4 = stream A of groups 0..4; rows 5..9 = stream B
    __shared__ __align__(16) float sh_h[2][NB][ROWP];
    __shared__ __align__(16) float sh_wout[ROWP];
    __shared__ __align__(16) float sh_bs[HID][4];   // per-unit gate biases
    __shared__ __align__(16) float sh_wi[HID][4];   // per-unit W_ih

    const int tid = threadIdx.x;
    int bl = tid / HID;              // group 0..4; 5 = filler lanes 250..255
    int j  = tid - bl * HID;         // hidden unit 0..49
    const bool lane_ok = (bl < NG);
    if (!lane_ok) { bl = 0; j = 0; }
    const int b0 = blockIdx.x * NB + bl;
    const int b1 = b0 + NG;
    const bool actA = lane_ok && (b0 < B);
    const bool actB = lane_ok && (b1 < B);

    // ---- one-time init ----
    for (int i = tid; i < 2 * NB * ROWP; i += BLOCK)
        (&sh_h[0][0][0])[i] = 0.0f;
    if (tid < ROWP)
        sh_wout[tid] = (tid < HID) ? W_out[tid] : 0.0f;
    if (tid < HID) {                 // group-0 lanes fill bias/Wih tables
        #pragma unroll
        for (int g = 0; g < 4; g++) {
            const int row = g * HID + tid;
            sh_bs[tid][g] = b_ih[row] + b_hh[row];
            sh_wi[tid][g] = W_ih[row];
        }
    }

    // 4 W_hh gate rows for unit j, f32 pairs (shared by both streams): 200 regs
    unsigned long long w2[4][25];
    #pragma unroll
    for (int g = 0; g < 4; g++) {
        const int row = g * HID + j;       // PyTorch gate order: i, f, g, o
        const unsigned long long* wrow =
            reinterpret_cast<const unsigned long long*>(W_hh + row * HID);
        #pragma unroll
        for (int p = 0; p < 25; p++)
            w2[g][p] = wrow[p];
    }
    const float bout = b_out[0];

    const float* __restrict__ xrowA = x + (size_t)(actA ? b0 : 0) * SEQT;
    const float* __restrict__ xrowB = x + (size_t)(actB ? b1 : 0) * SEQT;
    float* __restrict__ orowA = out + (size_t)(actA ? b0 : 0) * SEQT;
    float* __restrict__ orowB = out + (size_t)(actB ? b1 : 0) * SEQT;

    float cA = 0.0f, cB = 0.0f;
    int cur = 0;

    __syncthreads();

    for (int t = 0; t < SEQT; t++) {
        const int nxt = cur ^ 1;

        if (lane_ok) {
            // --- out[t-1] for group leaders, from the READ buffer (h_{t-1}).
            // Independent of everything below -> ptxas interleaves it into
            // the dot's dependency bubbles.
            if (j == 0 && t > 0) {
                const float* hpA = &sh_h[cur][bl][0];
                float yA0 = bout, yA1 = 0.0f, yA2 = 0.0f, yA3 = 0.0f;
                float yB0 = bout, yB1 = 0.0f, yB2 = 0.0f, yB3 = 0.0f;
                #pragma unroll
                for (int kq = 0; kq < 13; kq++) {   // pads are zero
                    const float4 wv = *reinterpret_cast<const float4*>(sh_wout + kq * 4);
                    const float4 hA = *reinterpret_cast<const float4*>(hpA + kq * 4);
                    const float4 hB = *reinterpret_cast<const float4*>(hpA + NG * ROWP + kq * 4);
                    yA0 = __fmaf_rn(hA.x, wv.x, yA0);
                    yA1 = __fmaf_rn(hA.y, wv.y, yA1);
                    yA2 = __fmaf_rn(hA.z, wv.z, yA2);
                    yA3 = __fmaf_rn(hA.w, wv.w, yA3);
                    yB0 = __fmaf_rn(hB.x, wv.x, yB0);
                    yB1 = __fmaf_rn(hB.y, wv.y, yB1);
                    yB2 = __fmaf_rn(hB.z, wv.z, yB2);
                    yB3 = __fmaf_rn(hB.w, wv.w, yB3);
                }
                if (actA) orowA[t - 1] = (yA0 + yA1) + (yA2 + yA3);
                if (actB) orowB[t - 1] = (yB0 + yB1) + (yB2 + yB3);
            }

            const float xA = xrowA[t];
            const float xB = xrowB[t];
            const float4 bsv = *reinterpret_cast<const float4*>(&sh_bs[j][0]);
            const float4 wiv = *reinterpret_cast<const float4*>(&sh_wi[j][0]);

            const float* hA = &sh_h[cur][bl][0];      // B row at +NG*ROWP
            unsigned long long a0=0ull,a1=0ull,a2=0ull,a3=0ull;
            unsigned long long e0=0ull,e1=0ull,e2=0ull,e3=0ull;

            #pragma unroll
            for (int q = 0; q < 12; q++) {
                const ulonglong2 hvA = *reinterpret_cast<const ulonglong2*>(hA + q * 4);
                const ulonglong2 hvB = *reinterpret_cast<const ulonglong2*>(hA + NG * ROWP + q * 4);
                a0 = fma2(hvA.x, w2[0][2*q],   a0);
                e0 = fma2(hvB.x, w2[0][2*q],   e0);
                a1 = fma2(hvA.x, w2[1][2*q],   a1);
                e1 = fma2(hvB.x, w2[1][2*q],   e1);
                a2 = fma2(hvA.x, w2[2][2*q],   a2);
                e2 = fma2(hvB.x, w2[2][2*q],   e2);
                a3 = fma2(hvA.x, w2[3][2*q],   a3);
                e3 = fma2(hvB.x, w2[3][2*q],   e3);
                a0 = fma2(hvA.y, w2[0][2*q+1], a0);
                e0 = fma2(hvB.y, w2[0][2*q+1], e0);
                a1 = fma2(hvA.y, w2[1][2*q+1], a1);
                e1 = fma2(hvB.y, w2[1][2*q+1], e1);
                a2 = fma2(hvA.y, w2[2][2*q+1], a2);
                e2 = fma2(hvB.y, w2[2][2*q+1], e2);
                a3 = fma2(hvA.y, w2[3][2*q+1], a3);
                e3 = fma2(hvB.y, w2[3][2*q+1], e3);
            }
            {
                const unsigned long long hvA =
                    *reinterpret_cast<const unsigned long long*>(hA + 48);
                const unsigned long long hvB =
                    *reinterpret_cast<const unsigned long long*>(hA + NG * ROWP + 48);
                a0 = fma2(hvA, w2[0][24], a0);
                e0 = fma2(hvB, w2[0][24], e0);
                a1 = fma2(hvA, w2[1][24], a1);
                e1 = fma2(hvB, w2[1][24], e1);
                a2 = fma2(hvA, w2[2][24], a2);
                e2 = fma2(hvB, w2[2][24], e2);
                a3 = fma2(hvA, w2[3][24], a3);
                e3 = fma2(hvB, w2[3][24], e3);
            }

            // stream A cell update
            {
                const float g0 = hsum2(a0) + __fmaf_rn(xA, wiv.x, bsv.x);
                const float g1 = hsum2(a1) + __fmaf_rn(xA, wiv.y, bsv.y);
                const float g2 = hsum2(a2) + __fmaf_rn(xA, wiv.z, bsv.z);
                const float g3 = hsum2(a3) + __fmaf_rn(xA, wiv.w, bsv.w);
                const float ig = sigapx(g0), fg = sigapx(g1);
                const float gg = tanhapx(g2), og = sigapx(g3);
                cA = __fmaf_rn(fg, cA, ig * gg);
                if (actA) sh_h[nxt][bl][j] = og * tanhapx(cA);
            }
            // stream B cell update
            {
                const float g0 = hsum2(e0) + __fmaf_rn(xB, wiv.x, bsv.x);
                const float g1 = hsum2(e1) + __fmaf_rn(xB, wiv.y, bsv.y);
                const float g2 = hsum2(e2) + __fmaf_rn(xB, wiv.z, bsv.z);
                const float g3 = hsum2(e3) + __fmaf_rn(xB, wiv.w, bsv.w);
                const float ig = sigapx(g0), fg = sigapx(g1);
                const float gg = tanhapx(g2), og = sigapx(g3);
                cB = __fmaf_rn(fg, cB, ig * gg);
                if (actB) sh_h[nxt][bl + NG][j] = og * tanhapx(cB);
            }
        }

        __syncthreads();
        cur = nxt;
    }

    // tail: out[T-1] from the final h buffer
    if (lane_ok && j == 0) {
        const float* hpA = &sh_h[cur][bl][0];
        float yA0 = bout, yA1 = 0.0f, yA2 = 0.0f, yA3 = 0.0f;
        float yB0 = bout, yB1 = 0.0f, yB2 = 0.0f, yB3 = 0.0f;
        #pragma unroll
        for (int kq = 0; kq < 13; kq++) {
            const float4 wv = *reinterpret_cast<const float4*>(sh_wout + kq * 4);
            const float4 hA = *reinterpret_cast<const float4*>(hpA + kq * 4);
            const float4 hB = *reinterpret_cast<const float4*>(hpA + NG * ROWP + kq * 4);
            yA0 = __fmaf_rn(hA.x, wv.x, yA0);
            yA1 = __fmaf_rn(hA.y, wv.y, yA1);
            yA2 = __fmaf_rn(hA.z, wv.z, yA2);
            yA3 = __fmaf_rn(hA.w, wv.w, yA3);
            yB0 = __fmaf_rn(hB.x, wv.x, yB0);
            yB1 = __fmaf_rn(hB.y, wv.y, yB1);
            yB2 = __fmaf_rn(hB.z, wv.z, yB2);
            yB3 = __fmaf_rn(hB.w, wv.w, yB3);
        }
        if (actA) orowA[SEQT - 1] = (yA0 + yA1) + (yA2 + yA3);
        if (actB) orowB[SEQT - 1] = (yB0 + yB1) + (yB2 + yB3);
    }
}

extern "C" void kernel_launch(void* const* d_in, const int* in_sizes, int n_in,
                              void* d_out, int out_size)
{
    const float* x     = (const float*)d_in[0];
    const float* W_ih  = (const float*)d_in[1];
    const float* W_hh  = (const float*)d_in[2];
    const float* b_ih  = (const float*)d_in[3];
    const float* b_hh  = (const float*)d_in[4];
    const float* W_out = (const float*)d_in[5];
    const float* b_out = (const float*)d_in[6];
    float* out = (float*)d_out;

    const int B = in_sizes[0] / SEQT;          // I == 1, x is [B, T, 1]
    const int grid = (B + NB - 1) / NB;
    lstm_fused_kernel<<<grid, BLOCK>>>(x, W_ih, W_hh, b_ih, b_hh, W_out, b_out, out, B);
}

// round 11
// speedup vs baseline: 1.3265x; 1.1009x over previous
#include <cuda_runtime.h>

#define HID   50
#define SEQT  512
#define NB    2            // batch elements per block (dual-stream threads)
#define BLOCK 64           // 2 warps; 50 gate lanes + 2 out lanes
#define ROWP  52           // padded h row (floats)

// packed 2xfp32 FMA: d = a*b + c
__device__ __forceinline__ unsigned long long fma2(unsigned long long a,
                                                   unsigned long long b,
                                                   unsigned long long c) {
    unsigned long long d;
    asm("fma.rn.f32x2 %0, %1, %2, %3;" : "=l"(d) : "l"(a), "l"(b), "l"(c));
    return d;
}
__device__ __forceinline__ float hsum2(unsigned long long v) {
    float lo, hi;
    asm("mov.b64 {%0, %1}, %2;" : "=f"(lo), "=f"(hi) : "l"(v));
    return lo + hi;
}
__device__ __forceinline__ float tanhapx(float x) {
    float y;
    asm("tanh.approx.f32 %0, %1;" : "=f"(y) : "f"(x));
    return y;
}
__device__ __forceinline__ float sigapx(float x) {
    return __fmaf_rn(0.5f, tanhapx(0.5f * x), 0.5f);
}

__global__ void __launch_bounds__(BLOCK, 1)
lstm_fused_kernel(const float* __restrict__ x,
                  const float* __restrict__ W_ih,
                  const float* __restrict__ W_hh,
                  const float* __restrict__ b_ih,
                  const float* __restrict__ b_hh,
                  const float* __restrict__ W_out,
                  const float* __restrict__ b_out,
                  float* __restrict__ out,
                  int B)
{
    // double-buffered h for the block's two batch elements
    __shared__ __align__(16) float sh_h[2][NB][ROWP];
    __shared__ __align__(16) float sh_wout[ROWP];
    __shared__ __align__(16) float sh_bs[HID][4];   // per-unit gate biases
    __shared__ __align__(16) float sh_wi[HID][4];   // per-unit W_ih

    const int tid = threadIdx.x;
    const int j   = tid;                 // hidden unit (gate lanes < 50)
    const bool gate_lane = (tid < HID);

    const int bA = blockIdx.x * NB;      // stream A elem
    const int bB = bA + 1;               // stream B elem
    const bool actA = (bA < B);
    const bool actB = (bB < B);

    // out lanes 50,51 -> elems A,B
    const int  os       = tid - HID;
    const bool out_lane = (!gate_lane) && (os < NB) && (bA + os < B);

    // ---- one-time init ----
    for (int i = tid; i < 2 * NB * ROWP; i += BLOCK)
        (&sh_h[0][0][0])[i] = 0.0f;
    if (tid < ROWP)
        sh_wout[tid] = (tid < HID) ? W_out[tid] : 0.0f;
    if (gate_lane) {
        #pragma unroll
        for (int g = 0; g < 4; g++) {
            const int row = g * HID + tid;
            sh_bs[tid][g] = b_ih[row] + b_hh[row];
            sh_wi[tid][g] = W_ih[row];
        }
    }

    // 4 W_hh gate rows for unit j, f32 pairs (shared by both streams): 200 regs
    unsigned long long w2[4][25];
    if (gate_lane) {
        #pragma unroll
        for (int g = 0; g < 4; g++) {
            const int row = g * HID + j;   // PyTorch gate order: i, f, g, o
            const unsigned long long* wrow =
                reinterpret_cast<const unsigned long long*>(W_hh + row * HID);
            #pragma unroll
            for (int p = 0; p < 25; p++)
                w2[g][p] = wrow[p];
        }
    }
    const float bout = b_out[0];

    const float* __restrict__ xrowA = x + (size_t)(actA ? bA : 0) * SEQT;
    const float* __restrict__ xrowB = x + (size_t)(actB ? bB : 0) * SEQT;
    float* __restrict__ orow = out + (size_t)(out_lane ? (bA + os) : 0) * SEQT;

    float cA = 0.0f, cB = 0.0f;
    int cur = 0;

    __syncthreads();    // 2-warp barrier: cheap

    for (int t = 0; t < SEQT; t++) {
        const int nxt = cur ^ 1;

        if (gate_lane) {
            const float xA = xrowA[t];
            const float xB = xrowB[t];
            const float4 bsv = *reinterpret_cast<const float4*>(&sh_bs[j][0]);
            const float4 wiv = *reinterpret_cast<const float4*>(&sh_wi[j][0]);

            const float* hA = &sh_h[cur][0][0];   // elem B row at +ROWP
            unsigned long long a0=0ull,a1=0ull,a2=0ull,a3=0ull;
            unsigned long long e0=0ull,e1=0ull,e2=0ull,e3=0ull;

            #pragma unroll
            for (int q = 0; q < 12; q++) {
                const ulonglong2 hvA = *reinterpret_cast<const ulonglong2*>(hA + q * 4);
                const ulonglong2 hvB = *reinterpret_cast<const ulonglong2*>(hA + ROWP + q * 4);
                a0 = fma2(hvA.x, w2[0][2*q],   a0);
                e0 = fma2(hvB.x, w2[0][2*q],   e0);
                a1 = fma2(hvA.x, w2[1][2*q],   a1);
                e1 = fma2(hvB.x, w2[1][2*q],   e1);
                a2 = fma2(hvA.x, w2[2][2*q],   a2);
                e2 = fma2(hvB.x, w2[2][2*q],   e2);
                a3 = fma2(hvA.x, w2[3][2*q],   a3);
                e3 = fma2(hvB.x, w2[3][2*q],   e3);
                a0 = fma2(hvA.y, w2[0][2*q+1], a0);
                e0 = fma2(hvB.y, w2[0][2*q+1], e0);
                a1 = fma2(hvA.y, w2[1][2*q+1], a1);
                e1 = fma2(hvB.y, w2[1][2*q+1], e1);
                a2 = fma2(hvA.y, w2[2][2*q+1], a2);
                e2 = fma2(hvB.y, w2[2][2*q+1], e2);
                a3 = fma2(hvA.y, w2[3][2*q+1], a3);
                e3 = fma2(hvB.y, w2[3][2*q+1], e3);
            }
            {
                const unsigned long long hvA =
                    *reinterpret_cast<const unsigned long long*>(hA + 48);
                const unsigned long long hvB =
                    *reinterpret_cast<const unsigned long long*>(hA + ROWP + 48);
                a0 = fma2(hvA, w2[0][24], a0);
                e0 = fma2(hvB, w2[0][24], e0);
                a1 = fma2(hvA, w2[1][24], a1);
                e1 = fma2(hvB, w2[1][24], e1);
                a2 = fma2(hvA, w2[2][24], a2);
                e2 = fma2(hvB, w2[2][24], e2);
                a3 = fma2(hvA, w2[3][24], a3);
                e3 = fma2(hvB, w2[3][24], e3);
            }

            // stream A cell update
            {
                const float g0 = hsum2(a0) + __fmaf_rn(xA, wiv.x, bsv.x);
                const float g1 = hsum2(a1) + __fmaf_rn(xA, wiv.y, bsv.y);
                const float g2 = hsum2(a2) + __fmaf_rn(xA, wiv.z, bsv.z);
                const float g3 = hsum2(a3) + __fmaf_rn(xA, wiv.w, bsv.w);
                const float ig = sigapx(g0), fg = sigapx(g1);
                const float gg = tanhapx(g2), og = sigapx(g3);
                cA = __fmaf_rn(fg, cA, ig * gg);
                if (actA) sh_h[nxt][0][j] = og * tanhapx(cA);
            }
            // stream B cell update
            {
                const float g0 = hsum2(e0) + __fmaf_rn(xB, wiv.x, bsv.x);
                const float g1 = hsum2(e1) + __fmaf_rn(xB, wiv.y, bsv.y);
                const float g2 = hsum2(e2) + __fmaf_rn(xB, wiv.z, bsv.z);
                const float g3 = hsum2(e3) + __fmaf_rn(xB, wiv.w, bsv.w);
                const float ig = sigapx(g0), fg = sigapx(g1);
                const float gg = tanhapx(g2), og = sigapx(g3);
                cB = __fmaf_rn(fg, cB, ig * gg);
                if (actB) sh_h[nxt][1][j] = og * tanhapx(cB);
            }
        } else if (out_lane && t > 0) {
            // out[t-1] from the READ buffer, concurrent with gate compute
            const float* hp = &sh_h[cur][os][0];
            float y0 = bout, y1 = 0.0f, y2 = 0.0f, y3 = 0.0f;
            #pragma unroll
            for (int kq = 0; kq < 13; kq++) {       // pads are zero in both
                const float4 hv = *reinterpret_cast<const float4*>(hp + kq * 4);
                const float4 wv = *reinterpret_cast<const float4*>(sh_wout + kq * 4);
                y0 = __fmaf_rn(hv.x, wv.x, y0);
                y1 = __fmaf_rn(hv.y, wv.y, y1);
                y2 = __fmaf_rn(hv.z, wv.z, y2);
                y3 = __fmaf_rn(hv.w, wv.w, y3);
            }
            orow[t - 1] = (y0 + y1) + (y2 + y3);
        }

        __syncthreads();
        cur = nxt;
    }

    // tail: out[T-1] from the final h buffer
    if (out_lane) {
        const float* hp = &sh_h[cur][os][0];
        float y0 = bout, y1 = 0.0f, y2 = 0.0f, y3 = 0.0f;
        #pragma unroll
        for (int kq = 0; kq < 13; kq++) {
            const float4 hv = *reinterpret_cast<const float4*>(hp + kq * 4);
            const float4 wv = *reinterpret_cast<const float4*>(sh_wout + kq * 4);
            y0 = __fmaf_rn(hv.x, wv.x, y0);
            y1 = __fmaf_rn(hv.y, wv.y, y1);
            y2 = __fmaf_rn(hv.z, wv.z, y2);
            y3 = __fmaf_rn(hv.w, wv.w, y3);
        }
        orow[SEQT - 1] = (y0 + y1) + (y2 + y3);
    }
}

extern "C" void kernel_launch(void* const* d_in, const int* in_sizes, int n_in,
                              void* d_out, int out_size)
{
    const float* x     = (const float*)d_in[0];
    const float* W_ih  = (const float*)d_in[1];
    const float* W_hh  = (const float*)d_in[2];
    const float* b_ih  = (const float*)d_in[3];
    const float* b_hh  = (const float*)d_in[4];
    const float* W_out = (const float*)d_in[5];
    const float* b_out = (const float*)d_in[6];
    float* out = (float*)d_out;

    const int B = in_sizes[0] / SEQT;          // I == 1, x is [B, T, 1]
    const int grid = (B + NB - 1) / NB;
    lstm_fused_kernel<<<grid, BLOCK>>>(x, W_ih, W_hh, b_ih, b_hh, W_out, b_out, out, B);
}

// round 12
// speedup vs baseline: 1.3689x; 1.0320x over previous
#include <cuda_runtime.h>

#define HID   50
#define SEQT  512
#define NGRP  2            // independent 64-thread groups per block
#define NB    4            // batch elements per block (2 per group)
#define BLOCK 128          // 4 warps -> SMSPs 0..3
#define ROWP  52           // padded h row (floats)

// packed 2xfp32 FMA: d = a*b + c
__device__ __forceinline__ unsigned long long fma2(unsigned long long a,
                                                   unsigned long long b,
                                                   unsigned long long c) {
    unsigned long long d;
    asm("fma.rn.f32x2 %0, %1, %2, %3;" : "=l"(d) : "l"(a), "l"(b), "l"(c));
    return d;
}
__device__ __forceinline__ float hsum2(unsigned long long v) {
    float lo, hi;
    asm("mov.b64 {%0, %1}, %2;" : "=f"(lo), "=f"(hi) : "l"(v));
    return lo + hi;
}
__device__ __forceinline__ float tanhapx(float x) {
    float y;
    asm("tanh.approx.f32 %0, %1;" : "=f"(y) : "f"(x));
    return y;
}
__device__ __forceinline__ float sigapx(float x) {
    return __fmaf_rn(0.5f, tanhapx(0.5f * x), 0.5f);
}
// named barrier over one 64-thread group (2 warps)
__device__ __forceinline__ void group_bar(int id) {
    asm volatile("bar.sync %0, 64;" :: "r"(id) : "memory");
}

__global__ void __launch_bounds__(BLOCK, 1)
lstm_fused_kernel(const float* __restrict__ x,
                  const float* __restrict__ W_ih,
                  const float* __restrict__ W_hh,
                  const float* __restrict__ b_ih,
                  const float* __restrict__ b_hh,
                  const float* __restrict__ W_out,
                  const float* __restrict__ b_out,
                  float* __restrict__ out,
                  int B)
{
    // per-group double-buffered h (2 elems each)
    __shared__ __align__(16) float sh_h[NGRP][2][2][ROWP];
    __shared__ __align__(16) float sh_wout[ROWP];
    __shared__ __align__(16) float sh_bs[HID][4];   // per-unit gate biases
    __shared__ __align__(16) float sh_wi[HID][4];   // per-unit W_ih

    const int tid = threadIdx.x;
    const int g   = tid >> 6;            // group 0..1 (warps {0,1} / {2,3})
    const int r   = tid & 63;            // lane within group
    const int j   = r;                   // hidden unit (gate lanes < 50)
    const bool gate_lane = (r < HID);

    const int bA = blockIdx.x * NB + g * 2;  // this group's stream A elem
    const int bB = bA + 1;
    const bool actA = (bA < B);
    const bool actB = (bB < B);

    // out lanes 50,51 of each group -> elems A,B
    const int  os       = r - HID;
    const bool out_lane = (!gate_lane) && (os < 2) && (bA + os < B);

    // ---- one-time init (block-wide) ----
    for (int i = tid; i < NGRP * 2 * 2 * ROWP; i += BLOCK)
        (&sh_h[0][0][0][0])[i] = 0.0f;
    if (tid < ROWP)
        sh_wout[tid] = (tid < HID) ? W_out[tid] : 0.0f;
    if (tid < HID) {
        #pragma unroll
        for (int gg = 0; gg < 4; gg++) {
            const int row = gg * HID + tid;
            sh_bs[tid][gg] = b_ih[row] + b_hh[row];
            sh_wi[tid][gg] = W_ih[row];
        }
    }

    // 4 W_hh gate rows for unit j, f32 pairs (shared by both streams): 200 regs
    unsigned long long w2[4][25];
    if (gate_lane) {
        #pragma unroll
        for (int gg = 0; gg < 4; gg++) {
            const int row = gg * HID + j;   // PyTorch gate order: i, f, g, o
            const unsigned long long* wrow =
                reinterpret_cast<const unsigned long long*>(W_hh + row * HID);
            #pragma unroll
            for (int p = 0; p < 25; p++)
                w2[gg][p] = wrow[p];
        }
    }
    const float bout = b_out[0];

    const float* __restrict__ xrowA = x + (size_t)(actA ? bA : 0) * SEQT;
    const float* __restrict__ xrowB = x + (size_t)(actB ? bB : 0) * SEQT;
    float* __restrict__ orow = out + (size_t)(out_lane ? (bA + os) : 0) * SEQT;

    float cA = 0.0f, cB = 0.0f;
    int cur = 0;

    __syncthreads();           // init visible to both groups (once)

    const int barid = g + 1;   // named barrier ids 1..2

    for (int t = 0; t < SEQT; t++) {
        const int nxt = cur ^ 1;

        if (gate_lane) {
            const float xA = xrowA[t];
            const float xB = xrowB[t];
            const float4 bsv = *reinterpret_cast<const float4*>(&sh_bs[j][0]);
            const float4 wiv = *reinterpret_cast<const float4*>(&sh_wi[j][0]);

            const float* hA = &sh_h[g][cur][0][0];   // elem B row at +ROWP
            unsigned long long a0=0ull,a1=0ull,a2=0ull,a3=0ull;
            unsigned long long e0=0ull,e1=0ull,e2=0ull,e3=0ull;

            #pragma unroll
            for (int q = 0; q < 12; q++) {
                const ulonglong2 hvA = *reinterpret_cast<const ulonglong2*>(hA + q * 4);
                const ulonglong2 hvB = *reinterpret_cast<const ulonglong2*>(hA + ROWP + q * 4);
                a0 = fma2(hvA.x, w2[0][2*q],   a0);
                e0 = fma2(hvB.x, w2[0][2*q],   e0);
                a1 = fma2(hvA.x, w2[1][2*q],   a1);
                e1 = fma2(hvB.x, w2[1][2*q],   e1);
                a2 = fma2(hvA.x, w2[2][2*q],   a2);
                e2 = fma2(hvB.x, w2[2][2*q],   e2);
                a3 = fma2(hvA.x, w2[3][2*q],   a3);
                e3 = fma2(hvB.x, w2[3][2*q],   e3);
                a0 = fma2(hvA.y, w2[0][2*q+1], a0);
                e0 = fma2(hvB.y, w2[0][2*q+1], e0);
                a1 = fma2(hvA.y, w2[1][2*q+1], a1);
                e1 = fma2(hvB.y, w2[1][2*q+1], e1);
                a2 = fma2(hvA.y, w2[2][2*q+1], a2);
                e2 = fma2(hvB.y, w2[2][2*q+1], e2);
                a3 = fma2(hvA.y, w2[3][2*q+1], a3);
                e3 = fma2(hvB.y, w2[3][2*q+1], e3);
            }
            {
                const unsigned long long hvA =
                    *reinterpret_cast<const unsigned long long*>(hA + 48);
                const unsigned long long hvB =
                    *reinterpret_cast<const unsigned long long*>(hA + ROWP + 48);
                a0 = fma2(hvA, w2[0][24], a0);
                e0 = fma2(hvB, w2[0][24], e0);
                a1 = fma2(hvA, w2[1][24], a1);
                e1 = fma2(hvB, w2[1][24], e1);
                a2 = fma2(hvA, w2[2][24], a2);
                e2 = fma2(hvB, w2[2][24], e2);
                a3 = fma2(hvA, w2[3][24], a3);
                e3 = fma2(hvB, w2[3][24], e3);
            }

            // stream A cell update
            {
                const float g0 = hsum2(a0) + __fmaf_rn(xA, wiv.x, bsv.x);
                const float g1 = hsum2(a1) + __fmaf_rn(xA, wiv.y, bsv.y);
                const float g2 = hsum2(a2) + __fmaf_rn(xA, wiv.z, bsv.z);
                const float g3 = hsum2(a3) + __fmaf_rn(xA, wiv.w, bsv.w);
                const float ig = sigapx(g0), fg = sigapx(g1);
                const float gg = tanhapx(g2), og = sigapx(g3);
                cA = __fmaf_rn(fg, cA, ig * gg);
                if (actA) sh_h[g][nxt][0][j] = og * tanhapx(cA);
            }
            // stream B cell update
            {
                const float g0 = hsum2(e0) + __fmaf_rn(xB, wiv.x, bsv.x);
                const float g1 = hsum2(e1) + __fmaf_rn(xB, wiv.y, bsv.y);
                const float g2 = hsum2(e2) + __fmaf_rn(xB, wiv.z, bsv.z);
                const float g3 = hsum2(e3) + __fmaf_rn(xB, wiv.w, bsv.w);
                const float ig = sigapx(g0), fg = sigapx(g1);
                const float gg = tanhapx(g2), og = sigapx(g3);
                cB = __fmaf_rn(fg, cB, ig * gg);
                if (actB) sh_h[g][nxt][1][j] = og * tanhapx(cB);
            }
        } else if (out_lane && t > 0) {
            // out[t-1] from the READ buffer, concurrent with gate compute
            const float* hp = &sh_h[g][cur][os][0];
            float y0 = bout, y1 = 0.0f, y2 = 0.0f, y3 = 0.0f;
            #pragma unroll
            for (int kq = 0; kq < 13; kq++) {       // pads are zero in both
                const float4 hv = *reinterpret_cast<const float4*>(hp + kq * 4);
                const float4 wv = *reinterpret_cast<const float4*>(sh_wout + kq * 4);
                y0 = __fmaf_rn(hv.x, wv.x, y0);
                y1 = __fmaf_rn(hv.y, wv.y, y1);
                y2 = __fmaf_rn(hv.z, wv.z, y2);
                y3 = __fmaf_rn(hv.w, wv.w, y3);
            }
            orow[t - 1] = (y0 + y1) + (y2 + y3);
        }

        group_bar(barid);      // only this group's 2 warps
        cur = nxt;
    }

    // tail: out[T-1] from the final h buffer
    if (out_lane) {
        const float* hp = &sh_h[g][cur][os][0];
        float y0 = bout, y1 = 0.0f, y2 = 0.0f, y3 = 0.0f;
        #pragma unroll
        for (int kq = 0; kq < 13; kq++) {
            const float4 hv = *reinterpret_cast<const float4*>(hp + kq * 4);
            const float4 wv = *reinterpret_cast<const float4*>(sh_wout + kq * 4);
            y0 = __fmaf_rn(hv.x, wv.x, y0);
            y1 = __fmaf_rn(hv.y, wv.y, y1);
            y2 = __fmaf_rn(hv.z, wv.z, y2);
            y3 = __fmaf_rn(hv.w, wv.w, y3);
        }
        orow[SEQT - 1] = (y0 + y1) + (y2 + y3);
    }
}

extern "C" void kernel_launch(void* const* d_in, const int* in_sizes, int n_in,
                              void* d_out, int out_size)
{
    const float* x     = (const float*)d_in[0];
    const float* W_ih  = (const float*)d_in[1];
    const float* W_hh  = (const float*)d_in[2];
    const float* b_ih  = (const float*)d_in[3];
    const float* b_hh  = (const float*)d_in[4];
    const float* W_out = (const float*)d_in[5];
    const float* b_out = (const float*)d_in[6];
    float* out = (float*)d_out;

    const int B = in_sizes[0] / SEQT;          // I == 1, x is [B, T, 1]
    const int grid = (B + NB - 1) / NB;
    lstm_fused_kernel<<<grid, BLOCK>>>(x, W_ih, W_hh, b_ih, b_hh, W_out, b_out, out, B);
}